// round 2
// baseline (speedup 1.0000x reference)
#include <cuda_runtime.h>
#include <cstdint>

// Problem dims
#define B_ 32
#define S_ 64
#define T_ 64
#define E_ 128
#define H_ 256
#define V_ 32000
#define FOURH 1024
#define MPAD 2048   // padded row count for GEMM tiles (2016 real decoder rows)

// -------- device scratch (allocation-free: __device__ globals) --------
__device__ float g_Xenc[MPAD * FOURH];   // enc_b + src_emb @ enc_Wih^T, rows r = s*32+b
__device__ float g_Xdec[MPAD * FOURH];   // dec_b + trg_emb @ dec_Wih^T, rows r = t*32+b
__device__ float g_hs[MPAD * H_];        // decoder hidden states, rows r = t*32+b  (pad rows stay 0)
__device__ float g_h[2][B_ * H_];        // ping-pong hidden state [b][u]
__device__ unsigned g_bar;               // grid barrier counter (zeroed each launch)

// -------- packed f32x2 helpers (sm_103a: FFMA2 restores full fp32 rate) --------
static __device__ __forceinline__ unsigned long long ffma2(unsigned long long a,
                                                           unsigned long long b,
                                                           unsigned long long c) {
    unsigned long long d;
    asm("fma.rn.f32x2 %0, %1, %2, %3;" : "=l"(d) : "l"(a), "l"(b), "l"(c));
    return d;
}
static __device__ __forceinline__ unsigned long long dup2(float a) {
    unsigned long long r;
    asm("mov.b64 %0, {%1, %1};" : "=l"(r) : "f"(a));
    return r;
}
static __device__ __forceinline__ float2 unpk(unsigned long long v) {
    float lo, hi;
    asm("mov.b64 {%0, %1}, %2;" : "=f"(lo), "=f"(hi) : "l"(v));
    return make_float2(lo, hi);
}

// =====================================================================
// init: zero barrier, zero h buffer 0, zero out[:, 0, :]
// =====================================================================
__global__ void init_kernel(float* __restrict__ out) {
    int gt = blockIdx.x * blockDim.x + threadIdx.x;
    if (gt == 0) g_bar = 0u;
    if (gt < (B_ * H_) / 4)
        ((float4*)g_h[0])[gt] = make_float4(0.f, 0.f, 0.f, 0.f);
    const int total = B_ * (V_ / 4);
    for (int i = gt; i < total; i += gridDim.x * blockDim.x) {
        int b  = i / (V_ / 4);
        int v4 = i - b * (V_ / 4);
        ((float4*)(out + (size_t)b * T_ * V_))[v4] = make_float4(0.f, 0.f, 0.f, 0.f);
    }
}

// =====================================================================
// Generic fp32 GEMM  C[M=2048, N] = A[M,KD] @ B[N,KD]^T (+bias)
//   MODE 0: A = gathered enc_emb rows (idx=src), C -> g_Xenc
//   MODE 1: A = gathered dec_emb rows (idx=trg, t clamped), C -> g_Xdec
//   MODE 2: A = g_hs, C -> out (scattered as out[b][t+1][v]), rows >= 2016 skipped
// Tiles: BM=BN=128, BK=16, 256 threads, 8x8 per thread, f32x2 packed FMA.
// =====================================================================
template <int MODE, int KD>
__global__ __launch_bounds__(256)
void gemm_kernel(const float* __restrict__ Amat, const int* __restrict__ idx,
                 const float* __restrict__ Bmat, const float* __restrict__ bias,
                 float* __restrict__ Cout) {
    __shared__ __align__(16) float As[16][132];
    __shared__ __align__(16) float Bs[16][132];

    const int tid = threadIdx.x;
    const int tx = tid & 15;        // N direction (8 cols each)
    const int ty = tid >> 4;        // M direction (8 rows each)
    const int n0 = blockIdx.x * 128;
    const int m0 = blockIdx.y * 128;

    const float* Abase = (MODE == 2) ? g_hs : Amat;

    const float* aP[2];
    const float* bP[2];
    int kq[2], rw[2];
#pragma unroll
    for (int l = 0; l < 2; l++) {
        int id = tid + l * 256;
        int r  = id >> 2;
        kq[l]  = (id & 3) * 4;
        rw[l]  = r;
        int rg = m0 + r;
        const float* ap;
        if (MODE == 0) {
            int s = rg >> 5, bb = rg & 31;
            ap = Abase + (size_t)idx[bb * 64 + s] * KD;
        } else if (MODE == 1) {
            int t = rg >> 5, bb = rg & 31;
            if (t > 62) t = 62;              // pad rows: harmless garbage, never read
            ap = Abase + (size_t)idx[bb * 64 + t] * KD;
        } else {
            ap = Abase + (size_t)rg * KD;    // pad rows of g_hs are zero
        }
        aP[l] = ap;
        bP[l] = Bmat + (size_t)(n0 + r) * KD;
    }

    unsigned long long acc[8][4];
#pragma unroll
    for (int i = 0; i < 8; i++)
#pragma unroll
        for (int j = 0; j < 4; j++) acc[i][j] = 0ull;

    float4 aR[2], bR[2];
#pragma unroll
    for (int l = 0; l < 2; l++) {
        aR[l] = *(const float4*)(aP[l] + kq[l]);
        bR[l] = *(const float4*)(bP[l] + kq[l]);
    }

    const int KT = KD / 16;
    for (int kt = 0; kt < KT; kt++) {
#pragma unroll
        for (int l = 0; l < 2; l++) {
            As[kq[l] + 0][rw[l]] = aR[l].x;
            As[kq[l] + 1][rw[l]] = aR[l].y;
            As[kq[l] + 2][rw[l]] = aR[l].z;
            As[kq[l] + 3][rw[l]] = aR[l].w;
            Bs[kq[l] + 0][rw[l]] = bR[l].x;
            Bs[kq[l] + 1][rw[l]] = bR[l].y;
            Bs[kq[l] + 2][rw[l]] = bR[l].z;
            Bs[kq[l] + 3][rw[l]] = bR[l].w;
        }
        __syncthreads();
        if (kt + 1 < KT) {
            int ko = (kt + 1) * 16;
#pragma unroll
            for (int l = 0; l < 2; l++) {
                aR[l] = *(const float4*)(aP[l] + ko + kq[l]);
                bR[l] = *(const float4*)(bP[l] + ko + kq[l]);
            }
        }
#pragma unroll
        for (int k = 0; k < 16; k++) {
            float4 a0 = *(const float4*)&As[k][ty * 8];
            float4 a1 = *(const float4*)&As[k][ty * 8 + 4];
            ulonglong2 b01 = *(const ulonglong2*)&Bs[k][tx * 8];
            ulonglong2 b23 = *(const ulonglong2*)&Bs[k][tx * 8 + 4];
            unsigned long long bp[4] = {b01.x, b01.y, b23.x, b23.y};
            float am[8] = {a0.x, a0.y, a0.z, a0.w, a1.x, a1.y, a1.z, a1.w};
#pragma unroll
            for (int mi = 0; mi < 8; mi++) {
                unsigned long long ad = dup2(am[mi]);
#pragma unroll
                for (int np = 0; np < 4; np++)
                    acc[mi][np] = ffma2(ad, bp[np], acc[mi][np]);
            }
        }
        __syncthreads();
    }

    float* cbase = (MODE == 0) ? g_Xenc : (MODE == 1) ? g_Xdec : Cout;
#pragma unroll
    for (int mi = 0; mi < 8; mi++) {
        int rg = m0 + ty * 8 + mi;
        if (MODE == 2 && rg >= 2016) continue;
        float* cptr;
        if (MODE == 2) {
            int bb = rg & 31, t = rg >> 5;
            cptr = cbase + (size_t)bb * ((size_t)T_ * V_) + (size_t)(t + 1) * V_;
        } else {
            cptr = cbase + (size_t)rg * FOURH;
        }
#pragma unroll
        for (int np = 0; np < 4; np++) {
            int n = n0 + tx * 8 + np * 2;
            float2 v = unpk(acc[mi][np]);
            float2 o;
            o.x = v.x + bias[n];
            o.y = v.y + bias[n + 1];
            *(float2*)(cptr + n) = o;
        }
    }
}

// =====================================================================
// Persistent LSTM recurrence: 128 CTAs x 256 threads (all co-resident).
// CTA owns 2 hidden units (8 gate rows of Whh in SMEM, loaded per phase).
// Thread (q = tid>>5, b = tid&31): gate row j = (q>>1)*256 + u0 + (q&1).
// Per step: stage h (via __ldcg, L1 persists within launch!) into SMEM,
// f32x2 dot over K=256, exchange 4 gates through SMEM, owners (q<2) keep c
// in a register across BOTH phases, write h to the ping-pong GMEM buffer,
// then atomic grid barrier.
// =====================================================================
__global__ __launch_bounds__(256)
void lstm_kernel(const float* __restrict__ WhhE, const float* __restrict__ WhhD) {
    __shared__ __align__(16) float Whs[8][256];
    __shared__ __align__(16) float hS[32][258];   // padded: 2-way max conflict on LDS.64
    __shared__ float gbuf[8][32];

    const int tid = threadIdx.x;
    const int b   = tid & 31;
    const int q   = tid >> 5;
    const int u0  = blockIdx.x * 2;
    const int gate = q >> 1, ul = q & 1;
    const int j   = gate * 256 + u0 + ul;
    const bool owner = (q < 2);
    const int uo  = u0 + q;              // owner's hidden unit (valid when owner)

    float c = 0.f;
    unsigned gen = 0;
    const unsigned nCTA = gridDim.x;

    // load encoder Whh rows for this CTA
    for (int i = tid; i < 8 * 256; i += 256) {
        int r = i >> 8, k = i & 255;
        int jr = (r >> 1) * 256 + u0 + (r & 1);
        Whs[r][k] = WhhE[jr * 256 + k];
    }
    __syncthreads();

    int stepIdx = 0;
    for (int phase = 0; phase < 2; phase++) {
        const int nsteps = (phase == 0) ? 64 : 63;
        const float* X = (phase == 0) ? g_Xenc : g_Xdec;
        for (int s = 0; s < nsteps; s++) {
            const int p = stepIdx & 1;
            // stage h[p] into SMEM (bypass L1: data written by other SMs this launch)
            const unsigned long long* hg = (const unsigned long long*)g_h[p];
#pragma unroll
            for (int i = tid; i < 4096; i += 256) {
                int bi = i >> 7;
                int ki = (i & 127) * 2;
                *(unsigned long long*)&hS[bi][ki] = __ldcg(&hg[i]);
            }
            __syncthreads();

            float xv = X[(size_t)((s << 5) + b) * FOURH + j];
            unsigned long long a2 = 0ull, b2 = 0ull;
#pragma unroll
            for (int k = 0; k < 256; k += 4) {
                ulonglong2 w2 = *(const ulonglong2*)&Whs[q][k];
                unsigned long long h01 = *(const unsigned long long*)&hS[b][k];
                unsigned long long h23 = *(const unsigned long long*)&hS[b][k + 2];
                a2 = ffma2(w2.x, h01, a2);
                b2 = ffma2(w2.y, h23, b2);
            }
            float2 pa = unpk(a2), pb = unpk(b2);
            gbuf[q][b] = xv + pa.x + pa.y + pb.x + pb.y;
            __syncthreads();

            if (owner) {
                float ig = gbuf[q][b];
                float fg = gbuf[q + 2][b];
                float gg = gbuf[q + 4][b];
                float og = gbuf[q + 6][b];
                float si = 1.f / (1.f + expf(-ig));
                float sf = 1.f / (1.f + expf(-fg));
                float so = 1.f / (1.f + expf(-og));
                c = sf * c + si * tanhf(gg);
                float hv = so * tanhf(c);
                g_h[p ^ 1][b * 256 + uo] = hv;
                if (phase == 1) g_hs[(size_t)((s << 5) + b) * H_ + uo] = hv;
                __threadfence();
            }
            __syncthreads();

            // grid barrier (counter zeroed by init kernel each launch)
            gen++;
            if (tid == 0) {
                __threadfence();
                atomicAdd(&g_bar, 1u);
                const unsigned target = gen * nCTA;
                while (*((volatile unsigned*)&g_bar) < target) __nanosleep(32);
                __threadfence();
            }
            __syncthreads();
            stepIdx++;
        }
        if (phase == 0) {
            // swap in decoder Whh (all threads past barrier, safe to overwrite)
            for (int i = tid; i < 8 * 256; i += 256) {
                int r = i >> 8, k = i & 255;
                int jr = (r >> 1) * 256 + u0 + (r & 1);
                Whs[r][k] = WhhD[jr * 256 + k];
            }
            __syncthreads();
        }
    }
}

// =====================================================================
extern "C" void kernel_launch(void* const* d_in, const int* in_sizes, int n_in,
                              void* d_out, int out_size) {
    const int*   src  = (const int*)d_in[0];
    const int*   trg  = (const int*)d_in[1];
    const float* eemb = (const float*)d_in[2];
    const float* eWih = (const float*)d_in[3];
    const float* eWhh = (const float*)d_in[4];
    const float* eb   = (const float*)d_in[5];
    const float* demb = (const float*)d_in[6];
    const float* dWih = (const float*)d_in[7];
    const float* dWhh = (const float*)d_in[8];
    const float* db   = (const float*)d_in[9];
    const float* fcW  = (const float*)d_in[10];
    const float* fcb  = (const float*)d_in[11];
    float* out = (float*)d_out;

    init_kernel<<<256, 256>>>(out);
    // Xih precompute: enc (M=2048,N=1024,K=128), dec (same, gather clamped)
    gemm_kernel<0, 128><<<dim3(8, 16), 256>>>(eemb, src, eWih, eb, nullptr);
    gemm_kernel<1, 128><<<dim3(8, 16), 256>>>(demb, trg, dWih, db, nullptr);
    // 127-step recurrence, persistent grid
    lstm_kernel<<<128, 256>>>(eWhh, dWhh);
    // FC: (M=2048 pad, N=32000, K=256) -> scattered into out[b][t+1][v]
    gemm_kernel<2, 256><<<dim3(250, 16), 256>>>(nullptr, nullptr, fcW, fcb, out);
}

// round 6
// speedup vs baseline: 1.0941x; 1.0941x over previous
#include <cuda_runtime.h>
#include <cstdint>

// Problem dims
#define B_ 32
#define S_ 64
#define T_ 64
#define E_ 128
#define H_ 256
#define V_ 32000
#define FOURH 1024
#define MPAD 2048   // padded row count for GEMM tiles (2016 real decoder rows)

// -------- device scratch (allocation-free: __device__ globals) --------
// __align__(16): these are read through float4* casts; natural alignment of
// float/float2 arrays is NOT contractually 16B.
__device__ __align__(16) float g_Xenc[MPAD * FOURH];   // enc_b + src_emb @ enc_Wih^T, rows r = s*32+b
__device__ __align__(16) float g_Xdec[MPAD * FOURH];   // dec_b + trg_emb @ dec_Wih^T, rows r = t*32+b
__device__ __align__(16) float g_hs[MPAD * H_];        // decoder hidden states, rows r = t*32+b (pad rows stay 0)
__device__ __align__(16) float2 g_hT[2][H_ / 2][B_];   // ping-pong hidden, TRANSPOSED+packed: [k2][b]
__device__ unsigned g_bar;                             // grid barrier counter (zeroed each launch)

// -------- packed f32x2 helpers (sm_103a FFMA2 = full fp32 rate) --------
static __device__ __forceinline__ unsigned long long ffma2(unsigned long long a,
                                                           unsigned long long b,
                                                           unsigned long long c) {
    unsigned long long d;
    asm("fma.rn.f32x2 %0, %1, %2, %3;" : "=l"(d) : "l"(a), "l"(b), "l"(c));
    return d;
}
static __device__ __forceinline__ unsigned long long dup2(float a) {
    unsigned long long r;
    asm("mov.b64 %0, {%1, %1};" : "=l"(r) : "f"(a));
    return r;
}
static __device__ __forceinline__ float2 unpk(unsigned long long v) {
    float lo, hi;
    asm("mov.b64 {%0, %1}, %2;" : "=f"(lo), "=f"(hi) : "l"(v));
    return make_float2(lo, hi);
}

// =====================================================================
// init: zero barrier, zero h ping buffer 0, zero out[:, 0, :]
// =====================================================================
__global__ void init_kernel(float* __restrict__ out) {
    int gt = blockIdx.x * blockDim.x + threadIdx.x;
    if (gt == 0) g_bar = 0u;
    if (gt < (H_ / 2) * B_)
        ((float2*)g_hT[0])[gt] = make_float2(0.f, 0.f);
    const int total = B_ * (V_ / 4);
    for (int i = gt; i < total; i += gridDim.x * blockDim.x) {
        int b  = i / (V_ / 4);
        int v4 = i - b * (V_ / 4);
        ((float4*)(out + (size_t)b * T_ * V_))[v4] = make_float4(0.f, 0.f, 0.f, 0.f);
    }
}

// =====================================================================
// Xih precompute GEMM  C[2048,1024] = gathered_emb @ Wih^T (+bias)
//   MODE 0: idx=src -> g_Xenc;  MODE 1: idx=trg (t clamped) -> g_Xdec
// BM=BN=128, BK=16, 256 threads, 8x8/thread, f32x2.
// SMEM stride 132 floats = 528B  (multiple of 16 -> 16B LDS legal here).
// =====================================================================
template <int MODE>
__global__ __launch_bounds__(256)
void xih_kernel(const float* __restrict__ Amat, const int* __restrict__ idx,
                const float* __restrict__ Bmat, const float* __restrict__ bias) {
    const int KD = 128;
    __shared__ __align__(16) float As[16][132];
    __shared__ __align__(16) float Bs[16][132];

    const int tid = threadIdx.x;
    const int tx = tid & 15;
    const int ty = tid >> 4;
    const int n0 = blockIdx.x * 128;
    const int m0 = blockIdx.y * 128;

    const float* aP[2];
    const float* bP[2];
    int kq[2], rw[2];
#pragma unroll
    for (int l = 0; l < 2; l++) {
        int id = tid + l * 256;
        int r  = id >> 2;
        kq[l]  = (id & 3) * 4;
        rw[l]  = r;
        int rg = m0 + r;
        int tt = rg >> 5, bb = rg & 31;
        if (MODE == 1 && tt > 62) tt = 62;   // pad rows: garbage ok, never read
        aP[l] = Amat + (size_t)idx[bb * 64 + tt] * KD;
        bP[l] = Bmat + (size_t)(n0 + r) * KD;
    }

    unsigned long long acc[8][4];
#pragma unroll
    for (int i = 0; i < 8; i++)
#pragma unroll
        for (int j = 0; j < 4; j++) acc[i][j] = 0ull;

    float4 aR[2], bR[2];
#pragma unroll
    for (int l = 0; l < 2; l++) {
        aR[l] = *(const float4*)(aP[l] + kq[l]);
        bR[l] = *(const float4*)(bP[l] + kq[l]);
    }

    const int KT = KD / 16;
    for (int kt = 0; kt < KT; kt++) {
#pragma unroll
        for (int l = 0; l < 2; l++) {
            As[kq[l] + 0][rw[l]] = aR[l].x;  As[kq[l] + 1][rw[l]] = aR[l].y;
            As[kq[l] + 2][rw[l]] = aR[l].z;  As[kq[l] + 3][rw[l]] = aR[l].w;
            Bs[kq[l] + 0][rw[l]] = bR[l].x;  Bs[kq[l] + 1][rw[l]] = bR[l].y;
            Bs[kq[l] + 2][rw[l]] = bR[l].z;  Bs[kq[l] + 3][rw[l]] = bR[l].w;
        }
        __syncthreads();
        if (kt + 1 < KT) {
            int ko = (kt + 1) * 16;
#pragma unroll
            for (int l = 0; l < 2; l++) {
                aR[l] = *(const float4*)(aP[l] + ko + kq[l]);
                bR[l] = *(const float4*)(bP[l] + ko + kq[l]);
            }
        }
#pragma unroll
        for (int k = 0; k < 16; k++) {
            float4 a0 = *(const float4*)&As[k][ty * 8];
            float4 a1 = *(const float4*)&As[k][ty * 8 + 4];
            ulonglong2 b01 = *(const ulonglong2*)&Bs[k][tx * 8];
            ulonglong2 b23 = *(const ulonglong2*)&Bs[k][tx * 8 + 4];
            unsigned long long bp[4] = {b01.x, b01.y, b23.x, b23.y};
            float am[8] = {a0.x, a0.y, a0.z, a0.w, a1.x, a1.y, a1.z, a1.w};
#pragma unroll
            for (int mi = 0; mi < 8; mi++) {
                unsigned long long ad = dup2(am[mi]);
#pragma unroll
                for (int np = 0; np < 4; np++)
                    acc[mi][np] = ffma2(ad, bp[np], acc[mi][np]);
            }
        }
        __syncthreads();
    }

    float* cbase = (MODE == 0) ? g_Xenc : g_Xdec;
#pragma unroll
    for (int mi = 0; mi < 8; mi++) {
        int rg = m0 + ty * 8 + mi;
        float* cptr = cbase + (size_t)rg * FOURH;
#pragma unroll
        for (int np = 0; np < 4; np++) {
            int n = n0 + tx * 8 + np * 2;
            float2 v = unpk(acc[mi][np]);
            float2 o; o.x = v.x + bias[n]; o.y = v.y + bias[n + 1];
            *(float2*)(cptr + n) = o;
        }
    }
}

// =====================================================================
// Persistent LSTM recurrence: 128 CTAs x 128 threads (4 warps), all
// co-resident. CTA owns 2 hidden units = 8 gate rows; warp w computes
// gate w for BOTH units (2 rows), reusing each h load twice.
// h layout: transposed+packed float2 hS[k2][b] -> conflict-free LDS.64,
// lane=b, broadcast weight loads (8B only -> alignment safe).
// Owners (warps 0,1) keep c in regs across both phases; raw-spin barrier.
// =====================================================================
__global__ __launch_bounds__(128)
void lstm_kernel(const float* __restrict__ WhhE, const float* __restrict__ WhhD) {
    __shared__ __align__(16) float Whs[4][2][256];   // [gate][ul][k]   8KB
    __shared__ __align__(16) float2 hS[128][32];     // [k2][b]        32KB
    __shared__ float gbuf[4][2][32];                 // [gate][ul][b]   1KB

    const int tid = threadIdx.x;
    const int b   = tid & 31;
    const int w   = tid >> 5;              // gate index 0..3
    const int u0  = blockIdx.x * 2;
    const int jA  = w * 256 + u0;          // gate row for unit u0
    const int jB  = jA + 1;                // gate row for unit u0+1

    float c = 0.f;                         // owner's cell state (warps 0,1)
    unsigned gen = 0;

    // load encoder Whh rows for this CTA
    for (int i = tid; i < 2048; i += 128) {
        int g = i >> 9, rem = i & 511, ul = rem >> 8, k = rem & 255;
        Whs[g][ul][k] = WhhE[(size_t)(g * 256 + u0 + ul) * 256 + k];
    }
    __syncthreads();

    int stepIdx = 0;
    for (int phase = 0; phase < 2; phase++) {
        const int nsteps = phase ? 63 : 64;
        const float* X = phase ? g_Xdec : g_Xenc;
        for (int s = 0; s < nsteps; s++) {
            const int p = stepIdx & 1;
            // stage h[p] (flat copy; __ldcg: data came from other SMs this launch)
            {
                const float4* src4 = (const float4*)&g_hT[p][0][0];
                float4* dst4 = (float4*)&hS[0][0];
#pragma unroll
                for (int i = 0; i < 16; i++)
                    dst4[tid + i * 128] = __ldcg(&src4[tid + i * 128]);
            }
            // prefetch x contributions (independent of h)
            size_t xrow = (size_t)((s << 5) + b) * FOURH;
            float xA = X[xrow + jA];
            float xB = X[xrow + jB];
            __syncthreads();

            unsigned long long accA = 0ull, accB = 0ull;
#pragma unroll 8
            for (int k2 = 0; k2 < 128; k2++) {
                unsigned long long h2 = *(const unsigned long long*)&hS[k2][b];
                unsigned long long wa = *(const unsigned long long*)&Whs[w][0][k2 * 2];
                unsigned long long wb = *(const unsigned long long*)&Whs[w][1][k2 * 2];
                accA = ffma2(wa, h2, accA);
                accB = ffma2(wb, h2, accB);
            }
            float2 va = unpk(accA), vb = unpk(accB);
            gbuf[w][0][b] = xA + va.x + va.y;
            gbuf[w][1][b] = xB + vb.x + vb.y;
            __syncthreads();

            if (w < 2) {   // owner of unit u0 + w, batch b
                float ig = gbuf[0][w][b];
                float fg = gbuf[1][w][b];
                float gg = gbuf[2][w][b];
                float og = gbuf[3][w][b];
                float si = 1.f / (1.f + __expf(-ig));
                float sf = 1.f / (1.f + __expf(-fg));
                float so = 1.f / (1.f + __expf(-og));
                c = sf * c + si * tanhf(gg);
                float hv = so * tanhf(c);
                ((float*)&g_hT[p ^ 1][blockIdx.x][b])[w] = hv;   // packed transposed
                if (phase) g_hs[(size_t)((s << 5) + b) * H_ + u0 + w] = hv;
                __threadfence();
            }
            __syncthreads();

            // grid barrier (counter zeroed each launch by init_kernel)
            gen++;
            if (tid == 0) {
                __threadfence();
                atomicAdd(&g_bar, 1u);
                const unsigned target = gen * 128u;
                while (*((volatile unsigned*)&g_bar) < target) { }
                __threadfence();
            }
            __syncthreads();
            stepIdx++;
        }
        if (!phase) {   // swap in decoder weights
            for (int i = tid; i < 2048; i += 128) {
                int g = i >> 9, rem = i & 511, ul = rem >> 8, k = rem & 255;
                Whs[g][ul][k] = WhhD[(size_t)(g * 256 + u0 + ul) * 256 + k];
            }
            __syncthreads();
        }
    }
}

// =====================================================================
// FC GEMM: out-scatter of g_hs[2048,256] @ fc_W[32000,256]^T + fc_b
// BM=128, BN=256, BK=16, 256 threads, 16x8 per-thread tile.
// SMEM strides 130/258 floats (== 2 mod 8 floats): conflict-free STS but
// only 8-byte aligned on odd k -> ALL tile-fragment LDS are 8B loads.
// A reads are warp-broadcast (free); per k: 12 LDS.64 vs 128 fma-cycles
// (64 FFMA2 @ rt2) -> fma-pipe bound.
// =====================================================================
__global__ __launch_bounds__(256)
void fc_kernel(const float* __restrict__ Bmat, const float* __restrict__ bias,
               float* __restrict__ out) {
    __shared__ __align__(16) float As[16][130];
    __shared__ __align__(16) float Bs[16][258];

    const int tid = threadIdx.x;
    const int tx = tid & 31;        // N: cols tx*4..+3 and 128+tx*4..+3
    const int ty = tid >> 5;        // M: rows ty*16..+15
    const int n0 = blockIdx.x * 256;
    const int m0 = blockIdx.y * 128;

    // A loaders: 2 slots/thread; B loaders: 4 slots/thread
    const float* aP[2]; int akq[2], arw[2];
#pragma unroll
    for (int l = 0; l < 2; l++) {
        int id = tid + l * 256;
        arw[l] = id >> 2;                 // 0..127
        akq[l] = (id & 3) * 4;
        aP[l]  = g_hs + (size_t)(m0 + arw[l]) * H_ + akq[l];
    }
    const float* bP[4]; int bkq[4], brw[4];
#pragma unroll
    for (int l = 0; l < 4; l++) {
        int id = tid + l * 256;
        brw[l] = id >> 2;                 // 0..255
        bkq[l] = (id & 3) * 4;
        bP[l]  = Bmat + (size_t)(n0 + brw[l]) * H_ + bkq[l];
    }

    unsigned long long acc[16][4];
#pragma unroll
    for (int i = 0; i < 16; i++)
#pragma unroll
        for (int j = 0; j < 4; j++) acc[i][j] = 0ull;

    float4 aR[2], bR[4];
#pragma unroll
    for (int l = 0; l < 2; l++) aR[l] = *(const float4*)(aP[l]);
#pragma unroll
    for (int l = 0; l < 4; l++) bR[l] = *(const float4*)(bP[l]);

    const int KT = H_ / 16;   // 16 k-tiles
    for (int kt = 0; kt < KT; kt++) {
#pragma unroll
        for (int l = 0; l < 2; l++) {
            As[akq[l] + 0][arw[l]] = aR[l].x;  As[akq[l] + 1][arw[l]] = aR[l].y;
            As[akq[l] + 2][arw[l]] = aR[l].z;  As[akq[l] + 3][arw[l]] = aR[l].w;
        }
#pragma unroll
        for (int l = 0; l < 4; l++) {
            Bs[bkq[l] + 0][brw[l]] = bR[l].x;  Bs[bkq[l] + 1][brw[l]] = bR[l].y;
            Bs[bkq[l] + 2][brw[l]] = bR[l].z;  Bs[bkq[l] + 3][brw[l]] = bR[l].w;
        }
        __syncthreads();
        if (kt + 1 < KT) {
            int ko = (kt + 1) * 16;
#pragma unroll
            for (int l = 0; l < 2; l++) aR[l] = *(const float4*)(aP[l] + ko);
#pragma unroll
            for (int l = 0; l < 4; l++) bR[l] = *(const float4*)(bP[l] + ko);
        }
#pragma unroll
        for (int k = 0; k < 16; k++) {
            // B fragment: 8 cols as 4 packed pairs — 8B loads (8B-aligned for all k)
            unsigned long long bp[4];
            bp[0] = *(const unsigned long long*)&Bs[k][tx * 4];
            bp[1] = *(const unsigned long long*)&Bs[k][tx * 4 + 2];
            bp[2] = *(const unsigned long long*)&Bs[k][128 + tx * 4];
            bp[3] = *(const unsigned long long*)&Bs[k][128 + tx * 4 + 2];
            // A fragment: 16 rows via 8 broadcast float2 loads
            float am[16];
#pragma unroll
            for (int h = 0; h < 8; h++) {
                float2 a2 = *(const float2*)&As[k][ty * 16 + h * 2];
                am[h * 2]     = a2.x;
                am[h * 2 + 1] = a2.y;
            }
#pragma unroll
            for (int mi = 0; mi < 16; mi++) {
                unsigned long long ad = dup2(am[mi]);
#pragma unroll
                for (int np = 0; np < 4; np++)
                    acc[mi][np] = ffma2(ad, bp[np], acc[mi][np]);
            }
        }
        __syncthreads();
    }

    // epilogue: bias + scatter out[b][t+1][v], skip pad rows (t=63)
    float4 bias0 = *(const float4*)(bias + n0 + tx * 4);
    float4 bias1 = *(const float4*)(bias + n0 + 128 + tx * 4);
#pragma unroll
    for (int mi = 0; mi < 16; mi++) {
        int rg = m0 + ty * 16 + mi;
        if (rg >= 2016) continue;
        int bb = rg & 31, t = rg >> 5;
        float* cptr = out + (size_t)bb * ((size_t)T_ * V_) + (size_t)(t + 1) * V_;
        float2 v0 = unpk(acc[mi][0]), v1 = unpk(acc[mi][1]);
        float2 v2 = unpk(acc[mi][2]), v3 = unpk(acc[mi][3]);
        float4 o0 = make_float4(v0.x + bias0.x, v0.y + bias0.y,
                                v1.x + bias0.z, v1.y + bias0.w);
        float4 o1 = make_float4(v2.x + bias1.x, v2.y + bias1.y,
                                v3.x + bias1.z, v3.y + bias1.w);
        *(float4*)(cptr + n0 + tx * 4)       = o0;
        *(float4*)(cptr + n0 + 128 + tx * 4) = o1;
    }
}

// =====================================================================
extern "C" void kernel_launch(void* const* d_in, const int* in_sizes, int n_in,
                              void* d_out, int out_size) {
    const int*   src  = (const int*)d_in[0];
    const int*   trg  = (const int*)d_in[1];
    const float* eemb = (const float*)d_in[2];
    const float* eWih = (const float*)d_in[3];
    const float* eWhh = (const float*)d_in[4];
    const float* eb   = (const float*)d_in[5];
    const float* demb = (const float*)d_in[6];
    const float* dWih = (const float*)d_in[7];
    const float* dWhh = (const float*)d_in[8];
    const float* db   = (const float*)d_in[9];
    const float* fcW  = (const float*)d_in[10];
    const float* fcb  = (const float*)d_in[11];
    float* out = (float*)d_out;

    init_kernel<<<256, 256>>>(out);
    xih_kernel<0><<<dim3(8, 16), 256>>>(eemb, src, eWih, eb);
    xih_kernel<1><<<dim3(8, 16), 256>>>(demb, trg, dWih, db);
    lstm_kernel<<<128, 128>>>(eWhh, dWhh);
    fc_kernel<<<dim3(125, 16), 256>>>(fcW, fcb, out);
}